// round 1
// baseline (speedup 1.0000x reference)
#include <cuda_runtime.h>
#include <math.h>
#include <stdint.h>

#define P 16384            // 128*128 pixels
#define OUTHALF 4194304    // 256*128*128

// ---------------- scratch (__device__ globals; no allocation allowed) ----------------
__device__ float g_Lt  [P * 256];      // low_level_feat transposed  [p][c]
__device__ float g_v   [256 * P];      // v (CHW) [c][p]
__device__ float g_u   [256 * P];      // u (CHW)
__device__ float g_ut  [P * 256];      // u transposed [p][c]
__device__ float g_xu  [256 * P];      // upsampled x (CHW)
__device__ float g_cc  [P * 512];      // concat [xu ; Cf] in NHWC [p][512]
__device__ float g_off [P * 20];       // offsets [p][18] (padded to 20)
__device__ float g_S2  [P * 4608];     // deform samples [p][n*512+c]  (302 MB)
__device__ float g_fam [P * 256];      // fam NHWC
__device__ float g_up1 [P * 256];      // up1 NHWC
__device__ float g_scr [P * 256];      // up2 NHWC (unused downstream)
__device__ float g_wre [4608 * 20];    // offset-conv weights reordered [(c*9+k)*20 + o]
__device__ float g_dre [256 * 4608];   // dc_w reordered [o][n*512+c]
__device__ float g_l1re[256 * 2304];   // lc1_w reordered [o][kk*256+c]
__device__ float g_l2re[256 * 2304];   // lc2_w reordered

// ---------------- weight reorders ----------------
__global__ void reorder_pw(const float* __restrict__ pw, float* __restrict__ wre) {
    int i = blockIdx.x * 256 + threadIdx.x;          // 4608*20
    int ck = i / 20, o = i % 20;
    wre[i] = (o < 18) ? pw[(size_t)o * 4608 + ck] : 0.f;
}
__global__ void reorder_dc(const float* __restrict__ dw, float* __restrict__ dre) {
    int i = blockIdx.x * 256 + threadIdx.x;          // 256*4608
    int o = i / 4608, k = i % 4608;
    int n = k / 512, c = k % 512;
    dre[i] = dw[(size_t)o * 4608 + c * 9 + n];
}
__global__ void reorder_lc(const float* __restrict__ lw, float* __restrict__ lre) {
    int i = blockIdx.x * 256 + threadIdx.x;          // 256*2304
    int o = i / 2304, k = i % 2304;
    int kk = k / 256, c = k % 256;
    lre[i] = lw[(size_t)o * 2304 + c * 9 + kk];
}

// ---------------- transpose CHW -> [p][c] (with dst ld/offset) ----------------
__global__ void transpose_cp(const float* __restrict__ src, float* __restrict__ dst,
                             int dstLd, int dstOff) {
    __shared__ float t[32][33];
    int p0 = blockIdx.x * 32, c0 = blockIdx.y * 32;
    int tx = threadIdx.x, ty = threadIdx.y;          // (32, 8)
#pragma unroll
    for (int j = 0; j < 4; j++)
        t[ty + j * 8][tx] = src[(size_t)(c0 + ty + j * 8) * P + p0 + tx];
    __syncthreads();
#pragma unroll
    for (int j = 0; j < 4; j++)
        dst[(size_t)(p0 + ty + j * 8) * dstLd + dstOff + c0 + tx] = t[tx][ty + j * 8];
}

// ---------------- bilinear upsample (align_corners) 32x32 -> 128x128, CHW ----------------
__global__ void upsample_k(const float* __restrict__ x, float* __restrict__ out) {
    int idx = blockIdx.x * 256 + threadIdx.x;        // 256 * 16384
    int c = idx >> 14, p = idx & 16383;
    int oy = p >> 7, ox = p & 127;
    const float s = 31.0f / 127.0f;
    float sy = oy * s, sx = ox * s;
    int y0 = (int)sy; int y1 = min(y0 + 1, 31);
    int x0 = (int)sx; int x1 = min(x0 + 1, 31);
    float wy = sy - (float)y0, wx = sx - (float)x0;
    const float* xc = x + (size_t)c * 1024;
    float a = xc[y0 * 32 + x0], b = xc[y0 * 32 + x1];
    float cm = xc[y1 * 32 + x0], d = xc[y1 * 32 + x1];
    float v0 = a * (1.f - wy) + cm * wy;
    float v1 = b * (1.f - wy) + d * wy;
    out[(size_t)c * P + p] = v0 * (1.f - wx) + v1 * wx;
}

// ---------------- per-channel 128x128x128 matmul: u = L@v + L ----------------
__global__ void __launch_bounds__(256, 2) bmm_u(const float* __restrict__ L,
                                                const float* __restrict__ v,
                                                float* __restrict__ u) {
    __shared__ float As[8][128];
    __shared__ float Bs[8][128];
    int c = blockIdx.x;
    const float* Lc = L + (size_t)c * P;
    const float* Vc = v + (size_t)c * P;
    float* Uc = u + (size_t)c * P;
    int tid = threadIdx.x;
    int tx = tid & 15, ty = tid >> 4, tm = ty * 8, tn = tx * 8;
    int arow = tid >> 1, ak = (tid & 1) * 4;
    int brow = tid >> 5, bn4 = (tid & 31) * 4;
    float acc[8][8];
#pragma unroll
    for (int i = 0; i < 8; i++)
#pragma unroll
        for (int j = 0; j < 8; j++) acc[i][j] = 0.f;

    for (int k0 = 0; k0 < 128; k0 += 8) {
        float4 av = *(const float4*)(Lc + arow * 128 + k0 + ak);
        As[ak + 0][arow] = av.x; As[ak + 1][arow] = av.y;
        As[ak + 2][arow] = av.z; As[ak + 3][arow] = av.w;
        float4 bv = *(const float4*)(Vc + (k0 + brow) * 128 + bn4);
        *(float4*)&Bs[brow][bn4] = bv;
        __syncthreads();
#pragma unroll
        for (int kk = 0; kk < 8; kk++) {
            float a[8], b[8];
            *(float4*)&a[0] = *(const float4*)&As[kk][tm];
            *(float4*)&a[4] = *(const float4*)&As[kk][tm + 4];
            *(float4*)&b[0] = *(const float4*)&Bs[kk][tn];
            *(float4*)&b[4] = *(const float4*)&Bs[kk][tn + 4];
#pragma unroll
            for (int i = 0; i < 8; i++)
#pragma unroll
                for (int j = 0; j < 8; j++)
                    acc[i][j] = fmaf(a[i], b[j], acc[i][j]);
        }
        __syncthreads();
    }
#pragma unroll
    for (int i = 0; i < 8; i++)
#pragma unroll
        for (int j = 0; j < 8; j++)
            Uc[(tm + i) * 128 + tn + j] = acc[i][j] + Lc[(tm + i) * 128 + tn + j];
}

// ---------------- generic NT SGEMM: C = A[M,K] * B[N,K]^T, fused epilogues ----------------
#define EPI_SIG 0   // C[m*N+n] = sigmoid(acc)                       (v)
#define EPI_CC  1   // C[m*ldc + coff + n] = acc                     (Cf -> cc)
#define EPI_FAM 2   // C[m*256+n] = acc + add[m*512+256+n]           (deform + Cf)
#define EPI_BN  3   // BN+ReLU -> C (NHWC) and Cchw (NCHW d_out)

template <int EPI, int GATHER>
__global__ void __launch_bounds__(256, 2) gemm_nt(
    const float* __restrict__ A, const float* __restrict__ B,
    int M, int N, int K,
    float* __restrict__ C, int ldc, int coff,
    const float* __restrict__ add,
    const float* __restrict__ gam, const float* __restrict__ bet,
    const float* __restrict__ mu, const float* __restrict__ var,
    float* __restrict__ Cchw) {
    __shared__ float As[8][128];
    __shared__ float Bs[8][128];
    int tid = threadIdx.x;
    int m0 = blockIdx.y * 128, n0 = blockIdx.x * 128;
    int tx = tid & 15, ty = tid >> 4;
    int tm = ty * 8, tn = tx * 8;
    int lrow = tid >> 1, lk = (tid & 1) * 4;
    float acc[8][8];
#pragma unroll
    for (int i = 0; i < 8; i++)
#pragma unroll
        for (int j = 0; j < 8; j++) acc[i][j] = 0.f;

    int gh = 0, gw = 0;
    if (GATHER) { int p = m0 + lrow; gh = p >> 7; gw = p & 127; }

    for (int k0 = 0; k0 < K; k0 += 8) {
        float4 av;
        if (!GATHER) {
            av = *(const float4*)(A + (size_t)(m0 + lrow) * K + (k0 + lk));
        } else {
            // A is an NHWC image [16384][256]; virtual K = kk*256 + c (3x3, pad 1)
            int kidx = k0 + lk;
            int kk = kidx >> 8, c = kidx & 255;
            int ih = gh + kk / 3 - 1, iw = gw + kk % 3 - 1;
            if (ih >= 0 && ih < 128 && iw >= 0 && iw < 128)
                av = *(const float4*)(A + (size_t)(ih * 128 + iw) * 256 + c);
            else
                av = make_float4(0.f, 0.f, 0.f, 0.f);
        }
        float4 bv = *(const float4*)(B + (size_t)(n0 + lrow) * K + (k0 + lk));
        As[lk + 0][lrow] = av.x; As[lk + 1][lrow] = av.y;
        As[lk + 2][lrow] = av.z; As[lk + 3][lrow] = av.w;
        Bs[lk + 0][lrow] = bv.x; Bs[lk + 1][lrow] = bv.y;
        Bs[lk + 2][lrow] = bv.z; Bs[lk + 3][lrow] = bv.w;
        __syncthreads();
#pragma unroll
        for (int kk = 0; kk < 8; kk++) {
            float a[8], b[8];
            *(float4*)&a[0] = *(const float4*)&As[kk][tm];
            *(float4*)&a[4] = *(const float4*)&As[kk][tm + 4];
            *(float4*)&b[0] = *(const float4*)&Bs[kk][tn];
            *(float4*)&b[4] = *(const float4*)&Bs[kk][tn + 4];
#pragma unroll
            for (int i = 0; i < 8; i++)
#pragma unroll
                for (int j = 0; j < 8; j++)
                    acc[i][j] = fmaf(a[i], b[j], acc[i][j]);
        }
        __syncthreads();
    }

    if (EPI == EPI_SIG) {
#pragma unroll
        for (int i = 0; i < 8; i++)
#pragma unroll
            for (int j = 0; j < 8; j++) {
                size_t idx = (size_t)(m0 + tm + i) * N + (n0 + tn + j);
                C[idx] = 1.f / (1.f + expf(-acc[i][j]));
            }
    } else if (EPI == EPI_CC) {
#pragma unroll
        for (int i = 0; i < 8; i++)
#pragma unroll
            for (int j = 0; j < 8; j++)
                C[(size_t)(m0 + tm + i) * ldc + coff + (n0 + tn + j)] = acc[i][j];
    } else if (EPI == EPI_FAM) {
#pragma unroll
        for (int i = 0; i < 8; i++)
#pragma unroll
            for (int j = 0; j < 8; j++) {
                size_t m = m0 + tm + i;
                int n = n0 + tn + j;
                C[m * 256 + n] = acc[i][j] + add[m * 512 + 256 + n];
            }
    } else {  // EPI_BN
        float sc[8], bb[8];
#pragma unroll
        for (int j = 0; j < 8; j++) {
            int o = n0 + tn + j;
            float s = gam[o] * rsqrtf(var[o] + 1e-5f);
            sc[j] = s;
            bb[j] = bet[o] - mu[o] * s;
        }
#pragma unroll
        for (int i = 0; i < 8; i++)
#pragma unroll
            for (int j = 0; j < 8; j++) {
                size_t m = m0 + tm + i;
                int o = n0 + tn + j;
                float y = fmaxf(fmaf(acc[i][j], sc[j], bb[j]), 0.f);
                C[m * 256 + o] = y;                 // NHWC scratch (next conv input)
                Cchw[(size_t)o * P + m] = y;        // NCHW output
            }
    }
}

// ---------------- offset conv: 3x3, 512 -> 18, padding 1, direct ----------------
__global__ void offset_conv(const float* __restrict__ cc, const float* __restrict__ wre,
                            const float* __restrict__ pb, float* __restrict__ off) {
    int p = blockIdx.x * 128 + threadIdx.x;
    int h = p >> 7, w = p & 127;
    float4 acc[5];
#pragma unroll
    for (int j = 0; j < 5; j++) acc[j] = make_float4(0.f, 0.f, 0.f, 0.f);

#pragma unroll
    for (int kh = 0; kh < 3; kh++) {
        int ih = h + kh - 1;
        if (ih < 0 || ih >= 128) continue;
#pragma unroll
        for (int kw = 0; kw < 3; kw++) {
            int iw = w + kw - 1;
            if (iw < 0 || iw >= 128) continue;
            int k = kh * 3 + kw;
            const float4* ccq = (const float4*)(cc + (size_t)(ih * 128 + iw) * 512);
            for (int c4 = 0; c4 < 128; c4++) {
                float4 vv = ccq[c4];
#pragma unroll
                for (int e = 0; e < 4; e++) {
                    float vs = (e == 0) ? vv.x : (e == 1) ? vv.y : (e == 2) ? vv.z : vv.w;
                    const float4* wp = (const float4*)(wre + ((size_t)((c4 * 4 + e) * 9 + k)) * 20);
#pragma unroll
                    for (int j = 0; j < 5; j++) {
                        float4 wj = wp[j];
                        acc[j].x = fmaf(vs, wj.x, acc[j].x);
                        acc[j].y = fmaf(vs, wj.y, acc[j].y);
                        acc[j].z = fmaf(vs, wj.z, acc[j].z);
                        acc[j].w = fmaf(vs, wj.w, acc[j].w);
                    }
                }
            }
        }
    }
    const float* af = (const float*)acc;
    float* op = off + (size_t)p * 20;
#pragma unroll
    for (int o = 0; o < 18; o++) op[o] = af[o] + pb[o];
}

// ---------------- deformable sampling -> S2[p][n*512+c] ----------------
__global__ void deform_sample(const float* __restrict__ cc, const float* __restrict__ off,
                              float* __restrict__ S2) {
    __shared__ int sidx[9][4];
    __shared__ float swt[9][4];
    int p = blockIdx.x;
    int tid = threadIdx.x;
    if (tid < 9) {
        int n = tid;
        int h = p >> 7, w = p & 127;
        float px = off[(size_t)p * 20 + n] + (float)(n / 3 - 1) + (float)(h + 1);
        float py = off[(size_t)p * 20 + 9 + n] + (float)(n % 3 - 1) + (float)(w + 1);
        float fx = floorf(px), fy = floorf(py);
        float x0 = fminf(fmaxf(fx, 0.f), 129.f);
        float x1 = fminf(fmaxf(fx + 1.f, 0.f), 129.f);
        float y0 = fminf(fmaxf(fy, 0.f), 129.f);
        float y1 = fminf(fmaxf(fy + 1.f, 0.f), 129.f);
        float pxc = fminf(fmaxf(px, 0.f), 129.f);
        float pyc = fminf(fmaxf(py, 0.f), 129.f);
        float glt = (1.f + (x0 - pxc)) * (1.f + (y0 - pyc));
        float grb = (1.f - (x1 - pxc)) * (1.f - (y1 - pyc));
        float glb = (1.f + (x0 - pxc)) * (1.f - (y1 - pyc));
        float grt = (1.f - (x1 - pxc)) * (1.f + (y0 - pyc));
        int ix0 = (int)x0, ix1 = (int)x1, iy0 = (int)y0, iy1 = (int)y1;
        int i00 = (ix0 >= 1 && ix0 <= 128 && iy0 >= 1 && iy0 <= 128) ? ((ix0 - 1) * 128 + (iy0 - 1)) : -1;
        int i11 = (ix1 >= 1 && ix1 <= 128 && iy1 >= 1 && iy1 <= 128) ? ((ix1 - 1) * 128 + (iy1 - 1)) : -1;
        int i01 = (ix0 >= 1 && ix0 <= 128 && iy1 >= 1 && iy1 <= 128) ? ((ix0 - 1) * 128 + (iy1 - 1)) : -1;
        int i10 = (ix1 >= 1 && ix1 <= 128 && iy0 >= 1 && iy0 <= 128) ? ((ix1 - 1) * 128 + (iy0 - 1)) : -1;
        sidx[n][0] = i00; swt[n][0] = glt;
        sidx[n][1] = i11; swt[n][1] = grb;
        sidx[n][2] = i01; swt[n][2] = glb;
        sidx[n][3] = i10; swt[n][3] = grt;
    }
    __syncthreads();
    const float4* cc4 = (const float4*)cc;
    float4* S4 = (float4*)S2;
#pragma unroll
    for (int n = 0; n < 9; n++) {
        float4 a = make_float4(0.f, 0.f, 0.f, 0.f);
#pragma unroll
        for (int t = 0; t < 4; t++) {
            int idx = sidx[n][t];
            float wt = swt[n][t];
            if (idx >= 0) {
                float4 v = cc4[(size_t)idx * 128 + tid];
                a.x = fmaf(wt, v.x, a.x);
                a.y = fmaf(wt, v.y, a.y);
                a.z = fmaf(wt, v.z, a.z);
                a.w = fmaf(wt, v.w, a.w);
            }
        }
        S4[(size_t)p * 1152 + n * 128 + tid] = a;
    }
}

// ---------------- launch ----------------
extern "C" void kernel_launch(void* const* d_in, const int* in_sizes, int n_in,
                              void* d_out, int out_size) {
    const float* x   = (const float*)d_in[0];
    const float* L   = (const float*)d_in[1];
    const float* fm  = (const float*)d_in[2];
    const float* fs  = (const float*)d_in[3];
    const float* pw  = (const float*)d_in[4];
    const float* pb  = (const float*)d_in[5];
    const float* dcw = (const float*)d_in[6];
    const float* lc1 = (const float*)d_in[7];
    const float* g1  = (const float*)d_in[8];
    const float* b1  = (const float*)d_in[9];
    const float* m1  = (const float*)d_in[10];
    const float* v1  = (const float*)d_in[11];
    const float* lc2 = (const float*)d_in[12];
    const float* g2  = (const float*)d_in[13];
    const float* b2  = (const float*)d_in[14];
    const float* m2  = (const float*)d_in[15];
    const float* v2  = (const float*)d_in[16];
    float* out = (float*)d_out;

    float *Lt, *vv, *uu, *ut, *xu, *cc, *off, *S2, *fam, *up1, *scr;
    float *wre, *dre, *l1re, *l2re;
    cudaGetSymbolAddress((void**)&Lt,   g_Lt);
    cudaGetSymbolAddress((void**)&vv,   g_v);
    cudaGetSymbolAddress((void**)&uu,   g_u);
    cudaGetSymbolAddress((void**)&ut,   g_ut);
    cudaGetSymbolAddress((void**)&xu,   g_xu);
    cudaGetSymbolAddress((void**)&cc,   g_cc);
    cudaGetSymbolAddress((void**)&off,  g_off);
    cudaGetSymbolAddress((void**)&S2,   g_S2);
    cudaGetSymbolAddress((void**)&fam,  g_fam);
    cudaGetSymbolAddress((void**)&up1,  g_up1);
    cudaGetSymbolAddress((void**)&scr,  g_scr);
    cudaGetSymbolAddress((void**)&wre,  g_wre);
    cudaGetSymbolAddress((void**)&dre,  g_dre);
    cudaGetSymbolAddress((void**)&l1re, g_l1re);
    cudaGetSymbolAddress((void**)&l2re, g_l2re);

    dim3 tb(32, 8);

    // weight reorders
    reorder_pw<<<360, 256>>>(pw, wre);
    reorder_dc<<<4608, 256>>>(dcw, dre);
    reorder_lc<<<2304, 256>>>(lc1, l1re);
    reorder_lc<<<2304, 256>>>(lc2, l2re);

    // Lt = L^T; xu = upsample(x); cc[:, 0:256] = xu^T
    transpose_cp<<<dim3(512, 8), tb>>>(L, Lt, 256, 0);
    upsample_k<<<16384, 256>>>(x, xu);
    transpose_cp<<<dim3(512, 8), tb>>>(xu, cc, 512, 0);

    // v = sigmoid(fm @ Z)  (CHW): M=256(o), N=16384(p), K=256, B = Lt
    gemm_nt<EPI_SIG, 0><<<dim3(128, 2), 256>>>(fm, Lt, 256, P, 256,
        vv, 0, 0, nullptr, nullptr, nullptr, nullptr, nullptr, nullptr);

    // u = L @ v + L (per-channel), then transpose to NHWC
    bmm_u<<<256, 256>>>(L, vv, uu);
    transpose_cp<<<dim3(512, 8), tb>>>(uu, ut, 256, 0);

    // Cf = fs @ u -> cc[:, 256:512]: M=16384(p), N=256(o), K=256
    gemm_nt<EPI_CC, 0><<<dim3(2, 128), 256>>>(ut, fs, P, 256, 256,
        cc, 512, 256, nullptr, nullptr, nullptr, nullptr, nullptr, nullptr);

    // offsets, deformable sampling
    offset_conv<<<128, 128>>>(cc, wre, pb, off);
    deform_sample<<<16384, 128>>>(cc, off, S2);

    // fam = deform_gemm + Cf: M=16384, N=256, K=4608
    gemm_nt<EPI_FAM, 0><<<dim3(2, 128), 256>>>(S2, dre, P, 256, 4608,
        fam, 256, 0, cc, nullptr, nullptr, nullptr, nullptr, nullptr);

    // up1 = relu(bn1(conv3x3(fam)))  [implicit-gather conv GEMM]
    gemm_nt<EPI_BN, 1><<<dim3(2, 128), 256>>>(fam, l1re, P, 256, 2304,
        up1, 0, 0, nullptr, g1, b1, m1, v1, out);

    // up2 = relu(bn2(conv3x3(up1)))
    gemm_nt<EPI_BN, 1><<<dim3(2, 128), 256>>>(up1, l2re, P, 256, 2304,
        scr, 0, 0, nullptr, g2, b2, m2, v2, out + OUTHALF);
}

// round 2
// speedup vs baseline: 1.0110x; 1.0110x over previous
#include <cuda_runtime.h>
#include <math.h>
#include <stdint.h>

#define P 16384            // 128*128 pixels
#define OUTHALF 4194304    // 256*128*128

typedef unsigned long long u64;

__device__ __forceinline__ u64 pk2(float lo, float hi) {
    u64 r; asm("mov.b64 %0,{%1,%2};" : "=l"(r) : "f"(lo), "f"(hi)); return r;
}
__device__ __forceinline__ void fma2(u64 &d, u64 a, u64 b) {
    asm("fma.rn.f32x2 %0,%1,%2,%0;" : "+l"(d) : "l"(a), "l"(b));
}
__device__ __forceinline__ float2 up2(u64 v) {
    float2 f; asm("mov.b64 {%0,%1},%2;" : "=f"(f.x), "=f"(f.y) : "l"(v)); return f;
}

// ---------------- scratch (__device__ globals; no allocation allowed) ----------------
__device__ float g_Lt  [P * 256];      // low_level_feat transposed  [p][c]
__device__ float g_v   [256 * P];      // v (CHW) [c][p]
__device__ float g_u   [256 * P];      // u (CHW)
__device__ float g_ut  [P * 256];      // u transposed [p][c]
__device__ float g_xu  [256 * P];      // upsampled x (CHW)
__device__ float g_cc  [P * 512];      // concat [xu ; Cf] in NHWC [p][512]
__device__ float g_off [P * 20];       // offsets [p][18] (padded to 20)
__device__ float g_S2  [P * 4608];     // deform samples [p][n*512+c]  (302 MB)
__device__ float g_fam [P * 256];      // fam NHWC
__device__ float g_up1 [P * 256];      // up1 NHWC
__device__ float g_scr [P * 256];      // up2 NHWC (unused downstream)
__device__ float g_wre [4608 * 20];    // offset-conv weights reordered [(c*9+k)*20 + o]
__device__ float g_dre [256 * 4608];   // dc_w reordered [o][n*512+c]
__device__ float g_l1re[256 * 2304];   // lc1_w reordered [o][kk*256+c]
__device__ float g_l2re[256 * 2304];   // lc2_w reordered

// ---------------- weight reorders ----------------
__global__ void reorder_pw(const float* __restrict__ pw, float* __restrict__ wre) {
    int i = blockIdx.x * 256 + threadIdx.x;          // 4608*20
    int ck = i / 20, o = i % 20;
    wre[i] = (o < 18) ? pw[(size_t)o * 4608 + ck] : 0.f;
}
__global__ void reorder_dc(const float* __restrict__ dw, float* __restrict__ dre) {
    int i = blockIdx.x * 256 + threadIdx.x;          // 256*4608
    int o = i / 4608, k = i % 4608;
    int n = k / 512, c = k % 512;
    dre[i] = dw[(size_t)o * 4608 + c * 9 + n];
}
__global__ void reorder_lc(const float* __restrict__ lw, float* __restrict__ lre) {
    int i = blockIdx.x * 256 + threadIdx.x;          // 256*2304
    int o = i / 2304, k = i % 2304;
    int kk = k / 256, c = k % 256;
    lre[i] = lw[(size_t)o * 2304 + c * 9 + kk];
}

// ---------------- transpose CHW -> [p][c] (with dst ld/offset) ----------------
__global__ void transpose_cp(const float* __restrict__ src, float* __restrict__ dst,
                             int dstLd, int dstOff) {
    __shared__ float t[32][33];
    int p0 = blockIdx.x * 32, c0 = blockIdx.y * 32;
    int tx = threadIdx.x, ty = threadIdx.y;          // (32, 8)
#pragma unroll
    for (int j = 0; j < 4; j++)
        t[ty + j * 8][tx] = src[(size_t)(c0 + ty + j * 8) * P + p0 + tx];
    __syncthreads();
#pragma unroll
    for (int j = 0; j < 4; j++)
        dst[(size_t)(p0 + ty + j * 8) * dstLd + dstOff + c0 + tx] = t[tx][ty + j * 8];
}

// ---------------- bilinear upsample (align_corners) 32x32 -> 128x128, CHW ----------------
__global__ void upsample_k(const float* __restrict__ x, float* __restrict__ out) {
    int idx = blockIdx.x * 256 + threadIdx.x;        // 256 * 16384
    int c = idx >> 14, p = idx & 16383;
    int oy = p >> 7, ox = p & 127;
    const float s = 31.0f / 127.0f;
    float sy = oy * s, sx = ox * s;
    int y0 = (int)sy; int y1 = min(y0 + 1, 31);
    int x0 = (int)sx; int x1 = min(x0 + 1, 31);
    float wy = sy - (float)y0, wx = sx - (float)x0;
    const float* xc = x + (size_t)c * 1024;
    float a = xc[y0 * 32 + x0], b = xc[y0 * 32 + x1];
    float cm = xc[y1 * 32 + x0], d = xc[y1 * 32 + x1];
    float v0 = a * (1.f - wy) + cm * wy;
    float v1 = b * (1.f - wy) + d * wy;
    out[(size_t)c * P + p] = v0 * (1.f - wx) + v1 * wx;
}

// ---------------- per-channel 128x128x128 matmul: u = L@v + L  (FFMA2, dbuf) ----------------
__global__ void __launch_bounds__(256, 2) bmm_u(const float* __restrict__ L,
                                                const float* __restrict__ v,
                                                float* __restrict__ u) {
    __shared__ float As[2][8][128];
    __shared__ float Bs[2][8][128];
    int c = blockIdx.x;
    const float* Lc = L + (size_t)c * P;
    const float* Vc = v + (size_t)c * P;
    float* Uc = u + (size_t)c * P;
    int tid = threadIdx.x;
    int tx = tid & 15, ty = tid >> 4, tm = ty * 8, tn = tx * 8;
    int arow = tid >> 1, ak = (tid & 1) * 4;
    int brow = tid >> 5, bn4 = (tid & 31) * 4;
    u64 acc2[8][4];
#pragma unroll
    for (int i = 0; i < 8; i++)
#pragma unroll
        for (int j = 0; j < 4; j++) acc2[i][j] = 0ull;

    float4 av = *(const float4*)(Lc + arow * 128 + ak);
    float4 bv = *(const float4*)(Vc + brow * 128 + bn4);
    As[0][ak + 0][arow] = av.x; As[0][ak + 1][arow] = av.y;
    As[0][ak + 2][arow] = av.z; As[0][ak + 3][arow] = av.w;
    *(float4*)&Bs[0][brow][bn4] = bv;
    __syncthreads();

    int buf = 0;
    for (int k0 = 0; k0 < 128; k0 += 8) {
        bool more = (k0 + 8) < 128;
        float4 a2, b2;
        if (more) {
            a2 = *(const float4*)(Lc + arow * 128 + k0 + 8 + ak);
            b2 = *(const float4*)(Vc + (k0 + 8 + brow) * 128 + bn4);
        }
#pragma unroll
        for (int kk = 0; kk < 8; kk++) {
            float a[8];
            *(float4*)&a[0] = *(const float4*)&As[buf][kk][tm];
            *(float4*)&a[4] = *(const float4*)&As[buf][kk][tm + 4];
            float4 b0 = *(const float4*)&Bs[buf][kk][tn];
            float4 b1 = *(const float4*)&Bs[buf][kk][tn + 4];
            u64 bb[4] = {pk2(b0.x, b0.y), pk2(b0.z, b0.w),
                         pk2(b1.x, b1.y), pk2(b1.z, b1.w)};
#pragma unroll
            for (int i = 0; i < 8; i++) {
                u64 ad = pk2(a[i], a[i]);
                fma2(acc2[i][0], ad, bb[0]);
                fma2(acc2[i][1], ad, bb[1]);
                fma2(acc2[i][2], ad, bb[2]);
                fma2(acc2[i][3], ad, bb[3]);
            }
        }
        if (more) {
            int nb = buf ^ 1;
            As[nb][ak + 0][arow] = a2.x; As[nb][ak + 1][arow] = a2.y;
            As[nb][ak + 2][arow] = a2.z; As[nb][ak + 3][arow] = a2.w;
            *(float4*)&Bs[nb][brow][bn4] = b2;
        }
        __syncthreads();
        buf ^= 1;
    }
#pragma unroll
    for (int i = 0; i < 8; i++)
#pragma unroll
        for (int j = 0; j < 4; j++) {
            float2 f = up2(acc2[i][j]);
            Uc[(tm + i) * 128 + tn + 2 * j]     = f.x + Lc[(tm + i) * 128 + tn + 2 * j];
            Uc[(tm + i) * 128 + tn + 2 * j + 1] = f.y + Lc[(tm + i) * 128 + tn + 2 * j + 1];
        }
}

// ---------------- generic NT SGEMM: C = A[M,K] * B[N,K]^T, FFMA2 + double buffer ----------------
#define EPI_SIG 0   // C[m*N+n] = sigmoid(acc)                       (v)
#define EPI_CC  1   // C[m*ldc + coff + n] = acc                     (Cf -> cc)
#define EPI_FAM 2   // C[m*256+n] = acc + add[m*512+256+n]           (deform + Cf)
#define EPI_BN  3   // BN+ReLU -> C (NHWC) and Cchw (NCHW d_out)

template <int EPI, int GATHER>
__global__ void __launch_bounds__(256, 2) gemm_nt(
    const float* __restrict__ A, const float* __restrict__ B,
    int M, int N, int K,
    float* __restrict__ C, int ldc, int coff,
    const float* __restrict__ add,
    const float* __restrict__ gam, const float* __restrict__ bet,
    const float* __restrict__ mu, const float* __restrict__ var,
    float* __restrict__ Cchw) {
    __shared__ float As[2][8][128];
    __shared__ float Bs[2][8][128];
    int tid = threadIdx.x;
    int m0 = blockIdx.y * 128, n0 = blockIdx.x * 128;
    int tx = tid & 15, ty = tid >> 4;
    int tm = ty * 8, tn = tx * 8;
    int lrow = tid >> 1, lk = (tid & 1) * 4;
    u64 acc2[8][4];
#pragma unroll
    for (int i = 0; i < 8; i++)
#pragma unroll
        for (int j = 0; j < 4; j++) acc2[i][j] = 0ull;

    int gh = 0, gw = 0;
    if (GATHER) { int p = m0 + lrow; gh = p >> 7; gw = p & 127; }

#define LOADA(K0, AV) do {                                                        \
        if (!GATHER) {                                                            \
            AV = *(const float4*)(A + (size_t)(m0 + lrow) * K + (K0) + lk);       \
        } else {                                                                  \
            int kidx = (K0) + lk;                                                 \
            int kq = kidx >> 8, cq = kidx & 255;                                  \
            int ih = gh + kq / 3 - 1, iw = gw + kq % 3 - 1;                       \
            if (ih >= 0 && ih < 128 && iw >= 0 && iw < 128)                       \
                AV = *(const float4*)(A + (size_t)(ih * 128 + iw) * 256 + cq);    \
            else AV = make_float4(0.f, 0.f, 0.f, 0.f);                            \
        } } while (0)

    float4 av, bv;
    LOADA(0, av);
    bv = *(const float4*)(B + (size_t)(n0 + lrow) * K + lk);
    As[0][lk + 0][lrow] = av.x; As[0][lk + 1][lrow] = av.y;
    As[0][lk + 2][lrow] = av.z; As[0][lk + 3][lrow] = av.w;
    Bs[0][lk + 0][lrow] = bv.x; Bs[0][lk + 1][lrow] = bv.y;
    Bs[0][lk + 2][lrow] = bv.z; Bs[0][lk + 3][lrow] = bv.w;
    __syncthreads();

    int buf = 0;
    for (int k0 = 0; k0 < K; k0 += 8) {
        bool more = (k0 + 8) < K;
        float4 a2, b2;
        if (more) {
            LOADA(k0 + 8, a2);
            b2 = *(const float4*)(B + (size_t)(n0 + lrow) * K + k0 + 8 + lk);
        }
#pragma unroll
        for (int kk = 0; kk < 8; kk++) {
            float a[8];
            *(float4*)&a[0] = *(const float4*)&As[buf][kk][tm];
            *(float4*)&a[4] = *(const float4*)&As[buf][kk][tm + 4];
            float4 b0 = *(const float4*)&Bs[buf][kk][tn];
            float4 b1 = *(const float4*)&Bs[buf][kk][tn + 4];
            u64 bb[4] = {pk2(b0.x, b0.y), pk2(b0.z, b0.w),
                         pk2(b1.x, b1.y), pk2(b1.z, b1.w)};
#pragma unroll
            for (int i = 0; i < 8; i++) {
                u64 ad = pk2(a[i], a[i]);
                fma2(acc2[i][0], ad, bb[0]);
                fma2(acc2[i][1], ad, bb[1]);
                fma2(acc2[i][2], ad, bb[2]);
                fma2(acc2[i][3], ad, bb[3]);
            }
        }
        if (more) {
            int nb = buf ^ 1;
            As[nb][lk + 0][lrow] = a2.x; As[nb][lk + 1][lrow] = a2.y;
            As[nb][lk + 2][lrow] = a2.z; As[nb][lk + 3][lrow] = a2.w;
            Bs[nb][lk + 0][lrow] = b2.x; Bs[nb][lk + 1][lrow] = b2.y;
            Bs[nb][lk + 2][lrow] = b2.z; Bs[nb][lk + 3][lrow] = b2.w;
        }
        __syncthreads();
        buf ^= 1;
    }
#undef LOADA

    float acc[8][8];
#pragma unroll
    for (int i = 0; i < 8; i++)
#pragma unroll
        for (int j = 0; j < 4; j++) {
            float2 f = up2(acc2[i][j]);
            acc[i][2 * j] = f.x; acc[i][2 * j + 1] = f.y;
        }

    if (EPI == EPI_SIG) {
#pragma unroll
        for (int i = 0; i < 8; i++)
#pragma unroll
            for (int j = 0; j < 8; j++) {
                size_t idx = (size_t)(m0 + tm + i) * N + (n0 + tn + j);
                C[idx] = 1.f / (1.f + expf(-acc[i][j]));
            }
    } else if (EPI == EPI_CC) {
#pragma unroll
        for (int i = 0; i < 8; i++)
#pragma unroll
            for (int j = 0; j < 8; j++)
                C[(size_t)(m0 + tm + i) * ldc + coff + (n0 + tn + j)] = acc[i][j];
    } else if (EPI == EPI_FAM) {
#pragma unroll
        for (int i = 0; i < 8; i++)
#pragma unroll
            for (int j = 0; j < 8; j++) {
                size_t m = m0 + tm + i;
                int n = n0 + tn + j;
                C[m * 256 + n] = acc[i][j] + add[m * 512 + 256 + n];
            }
    } else {  // EPI_BN
        float sc[8], bb2[8];
#pragma unroll
        for (int j = 0; j < 8; j++) {
            int o = n0 + tn + j;
            float s = gam[o] * rsqrtf(var[o] + 1e-5f);
            sc[j] = s;
            bb2[j] = bet[o] - mu[o] * s;
        }
#pragma unroll
        for (int i = 0; i < 8; i++)
#pragma unroll
            for (int j = 0; j < 8; j++) {
                size_t m = m0 + tm + i;
                int o = n0 + tn + j;
                float y = fmaxf(fmaf(acc[i][j], sc[j], bb2[j]), 0.f);
                C[m * 256 + o] = y;                 // NHWC scratch (next conv input)
                Cchw[(size_t)o * P + m] = y;        // NCHW output
            }
    }
}

// ---------------- offset conv: 3x3, 512 -> 18, padding 1, direct ----------------
__global__ void offset_conv(const float* __restrict__ cc, const float* __restrict__ wre,
                            const float* __restrict__ pb, float* __restrict__ off) {
    int p = blockIdx.x * 128 + threadIdx.x;
    int h = p >> 7, w = p & 127;
    float4 acc[5];
#pragma unroll
    for (int j = 0; j < 5; j++) acc[j] = make_float4(0.f, 0.f, 0.f, 0.f);

#pragma unroll
    for (int kh = 0; kh < 3; kh++) {
        int ih = h + kh - 1;
        if (ih < 0 || ih >= 128) continue;
#pragma unroll
        for (int kw = 0; kw < 3; kw++) {
            int iw = w + kw - 1;
            if (iw < 0 || iw >= 128) continue;
            int k = kh * 3 + kw;
            const float4* ccq = (const float4*)(cc + (size_t)(ih * 128 + iw) * 512);
            for (int c4 = 0; c4 < 128; c4++) {
                float4 vv = ccq[c4];
#pragma unroll
                for (int e = 0; e < 4; e++) {
                    float vs = (e == 0) ? vv.x : (e == 1) ? vv.y : (e == 2) ? vv.z : vv.w;
                    const float4* wp = (const float4*)(wre + ((size_t)((c4 * 4 + e) * 9 + k)) * 20);
#pragma unroll
                    for (int j = 0; j < 5; j++) {
                        float4 wj = wp[j];
                        acc[j].x = fmaf(vs, wj.x, acc[j].x);
                        acc[j].y = fmaf(vs, wj.y, acc[j].y);
                        acc[j].z = fmaf(vs, wj.z, acc[j].z);
                        acc[j].w = fmaf(vs, wj.w, acc[j].w);
                    }
                }
            }
        }
    }
    const float* af = (const float*)acc;
    float* op = off + (size_t)p * 20;
#pragma unroll
    for (int o = 0; o < 18; o++) op[o] = af[o] + pb[o];
}

// ---------------- deformable sampling -> S2[p][n*512+c] ----------------
__global__ void deform_sample(const float* __restrict__ cc, const float* __restrict__ off,
                              float* __restrict__ S2) {
    __shared__ int sidx[9][4];
    __shared__ float swt[9][4];
    int p = blockIdx.x;
    int tid = threadIdx.x;
    if (tid < 9) {
        int n = tid;
        int h = p >> 7, w = p & 127;
        float px = off[(size_t)p * 20 + n] + (float)(n / 3 - 1) + (float)(h + 1);
        float py = off[(size_t)p * 20 + 9 + n] + (float)(n % 3 - 1) + (float)(w + 1);
        float fx = floorf(px), fy = floorf(py);
        float x0 = fminf(fmaxf(fx, 0.f), 129.f);
        float x1 = fminf(fmaxf(fx + 1.f, 0.f), 129.f);
        float y0 = fminf(fmaxf(fy, 0.f), 129.f);
        float y1 = fminf(fmaxf(fy + 1.f, 0.f), 129.f);
        float pxc = fminf(fmaxf(px, 0.f), 129.f);
        float pyc = fminf(fmaxf(py, 0.f), 129.f);
        float glt = (1.f + (x0 - pxc)) * (1.f + (y0 - pyc));
        float grb = (1.f - (x1 - pxc)) * (1.f - (y1 - pyc));
        float glb = (1.f + (x0 - pxc)) * (1.f - (y1 - pyc));
        float grt = (1.f - (x1 - pxc)) * (1.f + (y0 - pyc));
        int ix0 = (int)x0, ix1 = (int)x1, iy0 = (int)y0, iy1 = (int)y1;
        int i00 = (ix0 >= 1 && ix0 <= 128 && iy0 >= 1 && iy0 <= 128) ? ((ix0 - 1) * 128 + (iy0 - 1)) : -1;
        int i11 = (ix1 >= 1 && ix1 <= 128 && iy1 >= 1 && iy1 <= 128) ? ((ix1 - 1) * 128 + (iy1 - 1)) : -1;
        int i01 = (ix0 >= 1 && ix0 <= 128 && iy1 >= 1 && iy1 <= 128) ? ((ix0 - 1) * 128 + (iy1 - 1)) : -1;
        int i10 = (ix1 >= 1 && ix1 <= 128 && iy0 >= 1 && iy0 <= 128) ? ((ix1 - 1) * 128 + (iy0 - 1)) : -1;
        sidx[n][0] = i00; swt[n][0] = glt;
        sidx[n][1] = i11; swt[n][1] = grb;
        sidx[n][2] = i01; swt[n][2] = glb;
        sidx[n][3] = i10; swt[n][3] = grt;
    }
    __syncthreads();
    const float4* cc4 = (const float4*)cc;
    float4* S4 = (float4*)S2;
#pragma unroll
    for (int n = 0; n < 9; n++) {
        float4 a = make_float4(0.f, 0.f, 0.f, 0.f);
#pragma unroll
        for (int t = 0; t < 4; t++) {
            int idx = sidx[n][t];
            float wt = swt[n][t];
            if (idx >= 0) {
                float4 v = cc4[(size_t)idx * 128 + tid];
                a.x = fmaf(wt, v.x, a.x);
                a.y = fmaf(wt, v.y, a.y);
                a.z = fmaf(wt, v.z, a.z);
                a.w = fmaf(wt, v.w, a.w);
            }
        }
        S4[(size_t)p * 1152 + n * 128 + tid] = a;
    }
}

// ---------------- launch ----------------
extern "C" void kernel_launch(void* const* d_in, const int* in_sizes, int n_in,
                              void* d_out, int out_size) {
    const float* x   = (const float*)d_in[0];
    const float* L   = (const float*)d_in[1];
    const float* fm  = (const float*)d_in[2];
    const float* fs  = (const float*)d_in[3];
    const float* pw  = (const float*)d_in[4];
    const float* pb  = (const float*)d_in[5];
    const float* dcw = (const float*)d_in[6];
    const float* lc1 = (const float*)d_in[7];
    const float* g1  = (const float*)d_in[8];
    const float* b1  = (const float*)d_in[9];
    const float* m1  = (const float*)d_in[10];
    const float* v1  = (const float*)d_in[11];
    const float* lc2 = (const float*)d_in[12];
    const float* g2  = (const float*)d_in[13];
    const float* b2  = (const float*)d_in[14];
    const float* m2  = (const float*)d_in[15];
    const float* v2  = (const float*)d_in[16];
    float* out = (float*)d_out;

    float *Lt, *vv, *uu, *ut, *xu, *cc, *off, *S2, *fam, *up1, *scr;
    float *wre, *dre, *l1re, *l2re;
    cudaGetSymbolAddress((void**)&Lt,   g_Lt);
    cudaGetSymbolAddress((void**)&vv,   g_v);
    cudaGetSymbolAddress((void**)&uu,   g_u);
    cudaGetSymbolAddress((void**)&ut,   g_ut);
    cudaGetSymbolAddress((void**)&xu,   g_xu);
    cudaGetSymbolAddress((void**)&cc,   g_cc);
    cudaGetSymbolAddress((void**)&off,  g_off);
    cudaGetSymbolAddress((void**)&S2,   g_S2);
    cudaGetSymbolAddress((void**)&fam,  g_fam);
    cudaGetSymbolAddress((void**)&up1,  g_up1);
    cudaGetSymbolAddress((void**)&scr,  g_scr);
    cudaGetSymbolAddress((void**)&wre,  g_wre);
    cudaGetSymbolAddress((void**)&dre,  g_dre);
    cudaGetSymbolAddress((void**)&l1re, g_l1re);
    cudaGetSymbolAddress((void**)&l2re, g_l2re);

    dim3 tb(32, 8);

    // weight reorders
    reorder_pw<<<360, 256>>>(pw, wre);
    reorder_dc<<<4608, 256>>>(dcw, dre);
    reorder_lc<<<2304, 256>>>(lc1, l1re);
    reorder_lc<<<2304, 256>>>(lc2, l2re);

    // Lt = L^T; xu = upsample(x); cc[:, 0:256] = xu^T
    transpose_cp<<<dim3(512, 8), tb>>>(L, Lt, 256, 0);
    upsample_k<<<16384, 256>>>(x, xu);
    transpose_cp<<<dim3(512, 8), tb>>>(xu, cc, 512, 0);

    // v = sigmoid(fm @ Z)  (CHW): M=256(o), N=16384(p), K=256, B = Lt
    gemm_nt<EPI_SIG, 0><<<dim3(128, 2), 256>>>(fm, Lt, 256, P, 256,
        vv, 0, 0, nullptr, nullptr, nullptr, nullptr, nullptr, nullptr);

    // u = L @ v + L (per-channel), then transpose to NHWC
    bmm_u<<<256, 256>>>(L, vv, uu);
    transpose_cp<<<dim3(512, 8), tb>>>(uu, ut, 256, 0);

    // Cf = fs @ u -> cc[:, 256:512]: M=16384(p), N=256(o), K=256
    gemm_nt<EPI_CC, 0><<<dim3(2, 128), 256>>>(ut, fs, P, 256, 256,
        cc, 512, 256, nullptr, nullptr, nullptr, nullptr, nullptr, nullptr);

    // offsets, deformable sampling
    offset_conv<<<128, 128>>>(cc, wre, pb, off);
    deform_sample<<<16384, 128>>>(cc, off, S2);

    // fam = deform_gemm + Cf: M=16384, N=256, K=4608
    gemm_nt<EPI_FAM, 0><<<dim3(2, 128), 256>>>(S2, dre, P, 256, 4608,
        fam, 256, 0, cc, nullptr, nullptr, nullptr, nullptr, nullptr);

    // up1 = relu(bn1(conv3x3(fam)))  [implicit-gather conv GEMM]
    gemm_nt<EPI_BN, 1><<<dim3(2, 128), 256>>>(fam, l1re, P, 256, 2304,
        up1, 0, 0, nullptr, g1, b1, m1, v1, out);

    // up2 = relu(bn2(conv3x3(up1)))
    gemm_nt<EPI_BN, 1><<<dim3(2, 128), 256>>>(up1, l2re, P, 256, 2304,
        scr, 0, 0, nullptr, g2, b2, m2, v2, out + OUTHALF);
}